// round 11
// baseline (speedup 1.0000x reference)
#include <cuda_runtime.h>
#include <cuda_fp16.h>

// ============================================================================
// UniGATConv on GB300 (R10):
//  - Xe stored as fp16 (only consumer is k_final; alpha comes from fp32 accs
//    in the GEMM epilogue) -> k_final gather traffic halved (327->164 MB).
//  - k_final: online single-pass softmax (max pass eliminated; one dependent
//    gather pass per vertex instead of two).
//  Launches: zero, hist, scan1, fill, sumx, gemm(+alpha), final  (7).
// ============================================================================

#define H_       8
#define C_       32
#define HC       256
#define IN_DIM   256
#define NMAX     50000
#define EMAX     10000
#define NNZMAX   320000
#define EB       ((EMAX + 1023) / 1024)   // 10 edge scan chunks
#define VB       ((NMAX + 1023) / 1024)   // 49 vertex scan chunks
#define NEG_SLOPE 0.2f

// ---- packed fp32x2 helpers (sm_100+ PTX; not emitted by ptxas from C++) ----
#define PACK2(d, lo, hi) asm("mov.b64 %0, {%1, %2};" : "=l"(d) : "f"(lo), "f"(hi))
#define FMA2(d, a, b)    asm("fma.rn.f32x2 %0, %1, %2, %0;" : "+l"(d) : "l"(a), "l"(b))
#define UNPACK2(lo, hi, s) asm("mov.b64 {%0, %1}, %2;" : "=f"(lo), "=f"(hi) : "l"(s))

// ---------------- scratch (static device globals; no allocations) -----------
__device__ int g_is64;
__device__ int g_scan_done;
__device__ int g_cnt_e[EMAX];
__device__ int g_off_e[EMAX];          // chunk-local exclusive prefix
__device__ int g_cnt_v[NMAX];
__device__ int g_off_v[NMAX];          // chunk-local exclusive prefix
__device__ int2 g_pack_e[NNZMAX];      // (edge id, rank within edge)
__device__ int2 g_pack_v[NNZMAX];      // (vertex id, rank within vertex)
__device__ int g_emem[NNZMAX];         // per-edge member vertex ids
__device__ int g_vmem[NNZMAX];         // per-vertex incident edge ids
__device__ __align__(16) float  g_SumX[EMAX * HC];  // mean_e(X)
__device__ __align__(16) __half g_Xe[EMAX * HC];    // edge features (fp16)
__device__ float g_alpha[EMAX * H_];                // leaky_relu(attention logit)
__device__ int g_bsum_e[EB];           // raw chunk sums -> exclusive prefixes
__device__ int g_bsum_v[VB];

__device__ __forceinline__ int wscan(int v) {   // warp inclusive scan
    int lane = threadIdx.x & 31;
#pragma unroll
    for (int o = 1; o < 32; o <<= 1) {
        int n = __shfl_up_sync(0xffffffffu, v, o);
        if (lane >= o) v += n;
    }
    return v;
}

// half2x2 (uint2) -> float4
__device__ __forceinline__ float4 xe_load(int e, int lane) {
    uint2 p = ((const uint2*)(g_Xe + e * HC))[lane];
    __half2 h0 = *reinterpret_cast<__half2*>(&p.x);
    __half2 h1 = *reinterpret_cast<__half2*>(&p.y);
    float2 f0 = __half22float2(h0);
    float2 f1 = __half22float2(h1);
    return make_float4(f0.x, f0.y, f1.x, f1.y);
}

// ---------------- zero counters + int64/int32 index detection ----------------
__global__ void k_zero(const int* idx32, int nnz, int E, int N) {
    if (blockIdx.x == 0) {
        __shared__ int any;
        if (threadIdx.x == 0) { any = 0; g_scan_done = 0; }
        __syncthreads();
        int lim = min(nnz / 2, 2048);
        for (int j = threadIdx.x; j < lim; j += blockDim.x)
            if (idx32[2 * j + 1] != 0) any = 1;   // benign race
        __syncthreads();
        if (threadIdx.x == 0) g_is64 = (any == 0) ? 1 : 0;
    }
    int i = blockIdx.x * blockDim.x + threadIdx.x;
    int stride = gridDim.x * blockDim.x;
    for (int j = i; j < E; j += stride) g_cnt_e[j] = 0;
    for (int j = i; j < N; j += stride) g_cnt_v[j] = 0;
}

__device__ __forceinline__ int load_idx(const void* p, int j, int is64) {
    return is64 ? (int)((const long long*)p)[j] : ((const int*)p)[j];
}

// -------- histogram, 4 elems/thread; atomic return value = rank --------------
__global__ void k_hist(const void* vert, const void* edges, int nnz) {
    int is64 = g_is64;
    int T = gridDim.x * blockDim.x;
    int i = blockIdx.x * blockDim.x + threadIdx.x;
    int j0 = i, j1 = i + T, j2 = i + 2 * T, j3 = i + 3 * T;
    bool b0 = j0 < nnz, b1 = j1 < nnz, b2 = j2 < nnz, b3 = j3 < nnz;
    int v0 = b0 ? load_idx(vert, j0, is64) : 0;
    int v1 = b1 ? load_idx(vert, j1, is64) : 0;
    int v2 = b2 ? load_idx(vert, j2, is64) : 0;
    int v3 = b3 ? load_idx(vert, j3, is64) : 0;
    int e0 = b0 ? load_idx(edges, j0, is64) : 0;
    int e1 = b1 ? load_idx(edges, j1, is64) : 0;
    int e2 = b2 ? load_idx(edges, j2, is64) : 0;
    int e3 = b3 ? load_idx(edges, j3, is64) : 0;
    if (b0) { int rv = atomicAdd(&g_cnt_v[v0], 1); int re = atomicAdd(&g_cnt_e[e0], 1);
              g_pack_v[j0] = make_int2(v0, rv); g_pack_e[j0] = make_int2(e0, re); }
    if (b1) { int rv = atomicAdd(&g_cnt_v[v1], 1); int re = atomicAdd(&g_cnt_e[e1], 1);
              g_pack_v[j1] = make_int2(v1, rv); g_pack_e[j1] = make_int2(e1, re); }
    if (b2) { int rv = atomicAdd(&g_cnt_v[v2], 1); int re = atomicAdd(&g_cnt_e[e2], 1);
              g_pack_v[j2] = make_int2(v2, rv); g_pack_e[j2] = make_int2(e2, re); }
    if (b3) { int rv = atomicAdd(&g_cnt_v[v3], 1); int re = atomicAdd(&g_cnt_e[e3], 1);
              g_pack_v[j3] = make_int2(v3, rv); g_pack_e[j3] = make_int2(e3, re); }
}

// ------- scan: chunk-local prefix; last block scans the chunk sums ------------
__global__ void k_scan1(int nE, int nV) {
    __shared__ int wsum[32];
    __shared__ int islast;
    bool isE  = blockIdx.x < EB;
    int chunk = isE ? blockIdx.x : blockIdx.x - EB;
    const int* cnt = isE ? g_cnt_e : g_cnt_v;
    int* off  = isE ? g_off_e : g_off_v;
    int* bsum = isE ? g_bsum_e : g_bsum_v;
    int n = isE ? nE : nV;
    int t = threadIdx.x, lane = t & 31, w = t >> 5;
    int idx = chunk * 1024 + t;
    int val = (idx < n) ? cnt[idx] : 0;
    int inc = wscan(val);
    if (lane == 31) wsum[w] = inc;
    __syncthreads();
    if (w == 0) wsum[lane] = wscan(wsum[lane]);
    __syncthreads();
    int pref = ((w > 0) ? wsum[w - 1] : 0) + inc - val;   // exclusive, chunk-local
    if (idx < n) off[idx] = pref;
    if (t == 1023) { bsum[chunk] = wsum[31]; __threadfence(); }
    __syncthreads();
    if (t == 0) islast = (atomicAdd(&g_scan_done, 1) == EB + VB - 1);
    __syncthreads();
    if (islast && w < 2) {
        __threadfence();   // acquire: see all blocks' bsum stores
        if (w == 0) {      // edges: EB <= 32, one warp-scan
            int v = (lane < EB) ? g_bsum_e[lane] : 0;
            int i2 = wscan(v);
            if (lane < EB) g_bsum_e[lane] = i2 - v;
        } else {           // vertices: VB <= 64, two tiles with carry
            int carry = 0;
#pragma unroll
            for (int tt = 0; tt < 2; tt++) {
                int id = tt * 32 + lane;
                int v = (id < VB) ? g_bsum_v[id] : 0;
                int i2 = wscan(v);
                if (id < VB) g_bsum_v[id] = carry + i2 - v;
                carry += __shfl_sync(0xffffffffu, i2, 31);
            }
        }
    }
}

// ------- fill member lists, 4 elems/thread, atomic-free -----------------------
__global__ void k_fill(int nnz) {
    int T = gridDim.x * blockDim.x;
    int i = blockIdx.x * blockDim.x + threadIdx.x;
    int j0 = i, j1 = i + T, j2 = i + 2 * T, j3 = i + 3 * T;
    bool b0 = j0 < nnz, b1 = j1 < nnz, b2 = j2 < nnz, b3 = j3 < nnz;
    int2 z = make_int2(0, 0);
    int2 pe0 = b0 ? g_pack_e[j0] : z, pv0 = b0 ? g_pack_v[j0] : z;
    int2 pe1 = b1 ? g_pack_e[j1] : z, pv1 = b1 ? g_pack_v[j1] : z;
    int2 pe2 = b2 ? g_pack_e[j2] : z, pv2 = b2 ? g_pack_v[j2] : z;
    int2 pe3 = b3 ? g_pack_e[j3] : z, pv3 = b3 ? g_pack_v[j3] : z;
    int oe0 = g_off_e[pe0.x] + g_bsum_e[pe0.x >> 10];
    int ov0 = g_off_v[pv0.x] + g_bsum_v[pv0.x >> 10];
    int oe1 = g_off_e[pe1.x] + g_bsum_e[pe1.x >> 10];
    int ov1 = g_off_v[pv1.x] + g_bsum_v[pv1.x >> 10];
    int oe2 = g_off_e[pe2.x] + g_bsum_e[pe2.x >> 10];
    int ov2 = g_off_v[pv2.x] + g_bsum_v[pv2.x >> 10];
    int oe3 = g_off_e[pe3.x] + g_bsum_e[pe3.x >> 10];
    int ov3 = g_off_v[pv3.x] + g_bsum_v[pv3.x >> 10];
    if (b0) { g_emem[oe0 + pe0.y] = pv0.x; g_vmem[ov0 + pv0.y] = pe0.x; }
    if (b1) { g_emem[oe1 + pe1.y] = pv1.x; g_vmem[ov1 + pv1.y] = pe1.x; }
    if (b2) { g_emem[oe2 + pe2.y] = pv2.x; g_vmem[ov2 + pv2.y] = pe2.x; }
    if (b3) { g_emem[oe3 + pe3.y] = pv3.x; g_vmem[ov3 + pv3.y] = pe3.x; }
}

// ---------------- per-edge mean of X (4 edges/block, 64 threads/edge, f4) -----
__global__ void k_sumx(const float* __restrict__ X) {
    int e = blockIdx.x * 4 + (threadIdx.x >> 6);
    int lane = threadIdx.x & 63;                   // channels [4*lane, 4*lane+4)
    int cnt = g_cnt_e[e];
    int base = g_off_e[e] + g_bsum_e[e >> 10];
    float4 a0 = make_float4(0.f, 0.f, 0.f, 0.f), a1 = a0, a2 = a0, a3 = a0;
    int j = 0;
    for (; j + 8 <= cnt; j += 8) {
        int v0 = g_emem[base + j + 0];
        int v1 = g_emem[base + j + 1];
        int v2 = g_emem[base + j + 2];
        int v3 = g_emem[base + j + 3];
        int v4 = g_emem[base + j + 4];
        int v5 = g_emem[base + j + 5];
        int v6 = g_emem[base + j + 6];
        int v7 = g_emem[base + j + 7];
        float4 x0 = ((const float4*)&X[v0 * IN_DIM])[lane];
        float4 x1 = ((const float4*)&X[v1 * IN_DIM])[lane];
        float4 x2 = ((const float4*)&X[v2 * IN_DIM])[lane];
        float4 x3 = ((const float4*)&X[v3 * IN_DIM])[lane];
        float4 x4 = ((const float4*)&X[v4 * IN_DIM])[lane];
        float4 x5 = ((const float4*)&X[v5 * IN_DIM])[lane];
        float4 x6 = ((const float4*)&X[v6 * IN_DIM])[lane];
        float4 x7 = ((const float4*)&X[v7 * IN_DIM])[lane];
        a0.x += x0.x + x4.x; a0.y += x0.y + x4.y; a0.z += x0.z + x4.z; a0.w += x0.w + x4.w;
        a1.x += x1.x + x5.x; a1.y += x1.y + x5.y; a1.z += x1.z + x5.z; a1.w += x1.w + x5.w;
        a2.x += x2.x + x6.x; a2.y += x2.y + x6.y; a2.z += x2.z + x6.z; a2.w += x2.w + x6.w;
        a3.x += x3.x + x7.x; a3.y += x3.y + x7.y; a3.z += x3.z + x7.z; a3.w += x3.w + x7.w;
    }
    for (; j + 4 <= cnt; j += 4) {
        int v0 = g_emem[base + j + 0];
        int v1 = g_emem[base + j + 1];
        int v2 = g_emem[base + j + 2];
        int v3 = g_emem[base + j + 3];
        float4 x0 = ((const float4*)&X[v0 * IN_DIM])[lane];
        float4 x1 = ((const float4*)&X[v1 * IN_DIM])[lane];
        float4 x2 = ((const float4*)&X[v2 * IN_DIM])[lane];
        float4 x3 = ((const float4*)&X[v3 * IN_DIM])[lane];
        a0.x += x0.x; a0.y += x0.y; a0.z += x0.z; a0.w += x0.w;
        a1.x += x1.x; a1.y += x1.y; a1.z += x1.z; a1.w += x1.w;
        a2.x += x2.x; a2.y += x2.y; a2.z += x2.z; a2.w += x2.w;
        a3.x += x3.x; a3.y += x3.y; a3.z += x3.z; a3.w += x3.w;
    }
    for (; j < cnt; j++) {
        float4 x0 = ((const float4*)&X[g_emem[base + j] * IN_DIM])[lane];
        a0.x += x0.x; a0.y += x0.y; a0.z += x0.z; a0.w += x0.w;
    }
    float inv = 1.0f / (float)(cnt > 0 ? cnt : 1);
    float4 r;
    r.x = (a0.x + a1.x + a2.x + a3.x) * inv;
    r.y = (a0.y + a1.y + a2.y + a3.y) * inv;
    r.z = (a0.z + a1.z + a2.z + a3.z) * inv;
    r.w = (a0.w + a1.w + a2.w + a3.w) * inv;
    ((float4*)&g_SumX[e * HC])[lane] = r;
}

// ------- Xe = SumX @ W^T + fused attention logits; Xe stored fp16 -------------
__global__ void k_gemm(const float* __restrict__ W, const float* __restrict__ att,
                       int E) {
    __shared__ __align__(16) float As[16][68];
    __shared__ __align__(16) float Bs[16][64];
    int tid = threadIdx.x;
    int tx = tid & 15, ty = tid >> 4;
    int lane = tid & 31;
    int row0 = blockIdx.y * 64, col0 = blockIdx.x * 64;
    unsigned long long c2[4][2] = {};
    int r = tid >> 2, sseg = tid & 3;
    float4 attv = *(const float4*)&att[col0 + tx * 4];

    for (int k0 = 0; k0 < IN_DIM; k0 += 16) {
        float4 av;
        int arow = row0 + r;
        if (arow < E) av = *(const float4*)&g_SumX[arow * HC + k0 + sseg * 4];
        else          av = make_float4(0.f, 0.f, 0.f, 0.f);
        As[sseg * 4 + 0][r] = av.x;
        As[sseg * 4 + 1][r] = av.y;
        As[sseg * 4 + 2][r] = av.z;
        As[sseg * 4 + 3][r] = av.w;
        float4 bv = *(const float4*)&W[(col0 + r) * IN_DIM + k0 + sseg * 4];
        Bs[sseg * 4 + 0][r] = bv.x;
        Bs[sseg * 4 + 1][r] = bv.y;
        Bs[sseg * 4 + 2][r] = bv.z;
        Bs[sseg * 4 + 3][r] = bv.w;
        __syncthreads();
#pragma unroll
        for (int kk = 0; kk < 16; kk++) {
            float4 a = *(const float4*)&As[kk][ty * 4];
            float4 b = *(const float4*)&Bs[kk][tx * 4];
            unsigned long long b01, b23, ap;
            PACK2(b01, b.x, b.y);
            PACK2(b23, b.z, b.w);
            PACK2(ap, a.x, a.x); FMA2(c2[0][0], ap, b01); FMA2(c2[0][1], ap, b23);
            PACK2(ap, a.y, a.y); FMA2(c2[1][0], ap, b01); FMA2(c2[1][1], ap, b23);
            PACK2(ap, a.z, a.z); FMA2(c2[2][0], ap, b01); FMA2(c2[2][1], ap, b23);
            PACK2(ap, a.w, a.w); FMA2(c2[3][0], ap, b01); FMA2(c2[3][1], ap, b23);
        }
        __syncthreads();
    }
#pragma unroll
    for (int i = 0; i < 4; i++) {
        int row = row0 + ty * 4 + i;
        float x0, x1, x2, x3;
        UNPACK2(x0, x1, c2[i][0]);
        UNPACK2(x2, x3, c2[i][1]);
        if (row < E) {
            __half2 h01 = __floats2half2_rn(x0, x1);
            __half2 h23 = __floats2half2_rn(x2, x3);
            uint2 st;
            st.x = *reinterpret_cast<unsigned*>(&h01);
            st.y = *reinterpret_cast<unsigned*>(&h23);
            *(uint2*)&g_Xe[row * HC + col0 + tx * 4] = st;
        }
        // fused alpha from fp32 accumulators
        float s = x0 * attv.x + x1 * attv.y + x2 * attv.z + x3 * attv.w;
        s += __shfl_xor_sync(0xffffffffu, s, 1);
        s += __shfl_xor_sync(0xffffffffu, s, 2);
        s += __shfl_xor_sync(0xffffffffu, s, 4);
        if ((lane & 7) == 0 && row < E) {
            int head = (col0 >> 5) + ((lane >> 3) & 1);
            g_alpha[row * H_ + head] = (s > 0.f) ? s : NEG_SLOPE * s;
        }
    }
}

// -------- per-vertex ONLINE softmax + weighted sum + L2 norm ------------------
// 4 vertices / block, 64 threads / vertex; single pass over incident edges.
__global__ void k_final(float* __restrict__ out, int N) {
    int g = threadIdx.x >> 6;                  // vertex slot in block (0..3)
    int v = blockIdx.x * 4 + g;
    int lane = threadIdx.x & 63;               // channels [4*lane, 4*lane+4)
    int h = lane >> 3;
    __shared__ float red[8];
    float4 val = make_float4(0.f, 0.f, 0.f, 0.f);
    int deg = g_cnt_v[v];
    int base = g_off_v[v] + g_bsum_v[v >> 10];
    if (deg > 0) {
        float m = -3.4e38f, s = 0.f;
        int j = 0;
        for (; j + 4 <= deg; j += 4) {
            int e0 = g_vmem[base + j + 0];
            int e1 = g_vmem[base + j + 1];
            int e2 = g_vmem[base + j + 2];
            int e3 = g_vmem[base + j + 3];
            float a0 = g_alpha[e0 * H_ + h];
            float a1 = g_alpha[e1 * H_ + h];
            float a2 = g_alpha[e2 * H_ + h];
            float a3 = g_alpha[e3 * H_ + h];
            float4 x0 = xe_load(e0, lane);
            float4 x1 = xe_load(e1, lane);
            float4 x2 = xe_load(e2, lane);
            float4 x3 = xe_load(e3, lane);
            float mb = fmaxf(fmaxf(a0, a1), fmaxf(a2, a3));
            float mn = fmaxf(m, mb);
            float sc = __expf(m - mn);     // 0 on first iteration (m = -inf-ish)
            float w0 = __expf(a0 - mn);
            float w1 = __expf(a1 - mn);
            float w2 = __expf(a2 - mn);
            float w3 = __expf(a3 - mn);
            s = s * sc + w0 + w1 + w2 + w3;
            val.x = fmaf(val.x, sc, w0 * x0.x + w1 * x1.x + w2 * x2.x + w3 * x3.x);
            val.y = fmaf(val.y, sc, w0 * x0.y + w1 * x1.y + w2 * x2.y + w3 * x3.y);
            val.z = fmaf(val.z, sc, w0 * x0.z + w1 * x1.z + w2 * x2.z + w3 * x3.z);
            val.w = fmaf(val.w, sc, w0 * x0.w + w1 * x1.w + w2 * x2.w + w3 * x3.w);
            m = mn;
        }
        for (; j < deg; j++) {
            int e = g_vmem[base + j];
            float a = g_alpha[e * H_ + h];
            float4 x = xe_load(e, lane);
            float mn = fmaxf(m, a);
            float sc = __expf(m - mn);
            float w = __expf(a - mn);
            s = s * sc + w;
            val.x = fmaf(val.x, sc, w * x.x);
            val.y = fmaf(val.y, sc, w * x.y);
            val.z = fmaf(val.z, sc, w * x.z);
            val.w = fmaf(val.w, sc, w * x.w);
            m = mn;
        }
        float inv = 1.0f / (s + 1e-16f);
        val.x *= inv; val.y *= inv; val.z *= inv; val.w *= inv;
    }
    float ss = val.x * val.x + val.y * val.y + val.z * val.z + val.w * val.w;
#pragma unroll
    for (int o = 16; o > 0; o >>= 1) ss += __shfl_down_sync(0xffffffffu, ss, o);
    if ((threadIdx.x & 31) == 0) red[threadIdx.x >> 5] = ss;
    __syncthreads();
    float tot = red[2 * g] + red[2 * g + 1];
    float scale = (tot > 0.f) ? rsqrtf(tot) : 0.f;
    val.x *= scale; val.y *= scale; val.z *= scale; val.w *= scale;
    ((float4*)&out[v * HC])[lane] = val;
}

// ---------------- host launch -------------------------------------------------
extern "C" void kernel_launch(void* const* d_in, const int* in_sizes, int n_in,
                              void* d_out, int out_size) {
    const float* X    = (const float*)d_in[0];
    const float* W    = (const float*)d_in[1];
    const float* att  = (const float*)d_in[2];
    const void*  vert = d_in[3];
    const void*  edge = d_in[4];

    int N   = in_sizes[0] / IN_DIM;
    int NNZ = in_sizes[3];
    int E   = EMAX;                 // fixed problem instance (num_edges = 10000)
    if (N   > NMAX)   N   = NMAX;
    if (NNZ > NNZMAX) NNZ = NNZMAX;

    k_zero<<<256, 256>>>((const int*)vert, NNZ, E, N);
    int g4 = ((NNZ + 3) / 4 + 255) / 256;      // 4 elems/thread
    k_hist<<<g4, 256>>>(vert, edge, NNZ);
    k_scan1<<<EB + VB, 1024>>>(E, N);
    k_fill<<<g4, 256>>>(NNZ);
    k_sumx<<<E / 4, 256>>>(X);
    dim3 gg(HC / 64, (E + 63) / 64);
    k_gemm<<<gg, 256>>>(W, att, E);
    k_final<<<N / 4, 256>>>((float*)d_out, N);
}

// round 12
// speedup vs baseline: 1.3746x; 1.3746x over previous
#include <cuda_runtime.h>
#include <cuda_fp16.h>

// ============================================================================
// UniGATConv on GB300 (R11):
//  - Keep fp16 g_Xe (k_final gather traffic halved, 327->164 MB; only consumer
//    is k_final, alpha computed from fp32 accumulators in gemm epilogue).
//  - REVERT k_final to the measured-good two-pass softmax (R9 structure):
//    the R10 online-softmax rescale recurrence added a loop-carried
//    MUFU/FMA chain that cancelled the traffic win.
//  - k_fill is the clock canary: unchanged since R9 (11.0 us at normal clock).
//  Launches: zero, hist, scan1, fill, sumx, gemm(+alpha), final  (7).
// ============================================================================

#define H_       8
#define C_       32
#define HC       256
#define IN_DIM   256
#define NMAX     50000
#define EMAX     10000
#define NNZMAX   320000
#define EB       ((EMAX + 1023) / 1024)   // 10 edge scan chunks
#define VB       ((NMAX + 1023) / 1024)   // 49 vertex scan chunks
#define NEG_SLOPE 0.2f

// ---- packed fp32x2 helpers (sm_100+ PTX; not emitted by ptxas from C++) ----
#define PACK2(d, lo, hi) asm("mov.b64 %0, {%1, %2};" : "=l"(d) : "f"(lo), "f"(hi))
#define FMA2(d, a, b)    asm("fma.rn.f32x2 %0, %1, %2, %0;" : "+l"(d) : "l"(a), "l"(b))
#define UNPACK2(lo, hi, s) asm("mov.b64 {%0, %1}, %2;" : "=f"(lo), "=f"(hi) : "l"(s))

// ---------------- scratch (static device globals; no allocations) -----------
__device__ int g_is64;
__device__ int g_scan_done;
__device__ int g_cnt_e[EMAX];
__device__ int g_off_e[EMAX];          // chunk-local exclusive prefix
__device__ int g_cnt_v[NMAX];
__device__ int g_off_v[NMAX];          // chunk-local exclusive prefix
__device__ int2 g_pack_e[NNZMAX];      // (edge id, rank within edge)
__device__ int2 g_pack_v[NNZMAX];      // (vertex id, rank within vertex)
__device__ int g_emem[NNZMAX];         // per-edge member vertex ids
__device__ int g_vmem[NNZMAX];         // per-vertex incident edge ids
__device__ __align__(16) float  g_SumX[EMAX * HC];  // mean_e(X)
__device__ __align__(16) __half g_Xe[EMAX * HC];    // edge features (fp16)
__device__ float g_alpha[EMAX * H_];                // leaky_relu(attention logit)
__device__ int g_bsum_e[EB];           // raw chunk sums -> exclusive prefixes
__device__ int g_bsum_v[VB];

__device__ __forceinline__ int wscan(int v) {   // warp inclusive scan
    int lane = threadIdx.x & 31;
#pragma unroll
    for (int o = 1; o < 32; o <<= 1) {
        int n = __shfl_up_sync(0xffffffffu, v, o);
        if (lane >= o) v += n;
    }
    return v;
}

// half2x2 (uint2, 8B coalesced) -> float4
__device__ __forceinline__ float4 xe_load(int e, int lane) {
    uint2 p = ((const uint2*)(g_Xe + e * HC))[lane];
    __half2 h0 = *reinterpret_cast<__half2*>(&p.x);
    __half2 h1 = *reinterpret_cast<__half2*>(&p.y);
    float2 f0 = __half22float2(h0);
    float2 f1 = __half22float2(h1);
    return make_float4(f0.x, f0.y, f1.x, f1.y);
}

// ---------------- zero counters + int64/int32 index detection ----------------
__global__ void k_zero(const int* idx32, int nnz, int E, int N) {
    if (blockIdx.x == 0) {
        __shared__ int any;
        if (threadIdx.x == 0) { any = 0; g_scan_done = 0; }
        __syncthreads();
        int lim = min(nnz / 2, 2048);
        for (int j = threadIdx.x; j < lim; j += blockDim.x)
            if (idx32[2 * j + 1] != 0) any = 1;   // benign race
        __syncthreads();
        if (threadIdx.x == 0) g_is64 = (any == 0) ? 1 : 0;
    }
    int i = blockIdx.x * blockDim.x + threadIdx.x;
    int stride = gridDim.x * blockDim.x;
    for (int j = i; j < E; j += stride) g_cnt_e[j] = 0;
    for (int j = i; j < N; j += stride) g_cnt_v[j] = 0;
}

__device__ __forceinline__ int load_idx(const void* p, int j, int is64) {
    return is64 ? (int)((const long long*)p)[j] : ((const int*)p)[j];
}

// -------- histogram, 4 elems/thread; atomic return value = rank --------------
__global__ void k_hist(const void* vert, const void* edges, int nnz) {
    int is64 = g_is64;
    int T = gridDim.x * blockDim.x;
    int i = blockIdx.x * blockDim.x + threadIdx.x;
    int j0 = i, j1 = i + T, j2 = i + 2 * T, j3 = i + 3 * T;
    bool b0 = j0 < nnz, b1 = j1 < nnz, b2 = j2 < nnz, b3 = j3 < nnz;
    int v0 = b0 ? load_idx(vert, j0, is64) : 0;
    int v1 = b1 ? load_idx(vert, j1, is64) : 0;
    int v2 = b2 ? load_idx(vert, j2, is64) : 0;
    int v3 = b3 ? load_idx(vert, j3, is64) : 0;
    int e0 = b0 ? load_idx(edges, j0, is64) : 0;
    int e1 = b1 ? load_idx(edges, j1, is64) : 0;
    int e2 = b2 ? load_idx(edges, j2, is64) : 0;
    int e3 = b3 ? load_idx(edges, j3, is64) : 0;
    if (b0) { int rv = atomicAdd(&g_cnt_v[v0], 1); int re = atomicAdd(&g_cnt_e[e0], 1);
              g_pack_v[j0] = make_int2(v0, rv); g_pack_e[j0] = make_int2(e0, re); }
    if (b1) { int rv = atomicAdd(&g_cnt_v[v1], 1); int re = atomicAdd(&g_cnt_e[e1], 1);
              g_pack_v[j1] = make_int2(v1, rv); g_pack_e[j1] = make_int2(e1, re); }
    if (b2) { int rv = atomicAdd(&g_cnt_v[v2], 1); int re = atomicAdd(&g_cnt_e[e2], 1);
              g_pack_v[j2] = make_int2(v2, rv); g_pack_e[j2] = make_int2(e2, re); }
    if (b3) { int rv = atomicAdd(&g_cnt_v[v3], 1); int re = atomicAdd(&g_cnt_e[e3], 1);
              g_pack_v[j3] = make_int2(v3, rv); g_pack_e[j3] = make_int2(e3, re); }
}

// ------- scan: chunk-local prefix; last block scans the chunk sums ------------
__global__ void k_scan1(int nE, int nV) {
    __shared__ int wsum[32];
    __shared__ int islast;
    bool isE  = blockIdx.x < EB;
    int chunk = isE ? blockIdx.x : blockIdx.x - EB;
    const int* cnt = isE ? g_cnt_e : g_cnt_v;
    int* off  = isE ? g_off_e : g_off_v;
    int* bsum = isE ? g_bsum_e : g_bsum_v;
    int n = isE ? nE : nV;
    int t = threadIdx.x, lane = t & 31, w = t >> 5;
    int idx = chunk * 1024 + t;
    int val = (idx < n) ? cnt[idx] : 0;
    int inc = wscan(val);
    if (lane == 31) wsum[w] = inc;
    __syncthreads();
    if (w == 0) wsum[lane] = wscan(wsum[lane]);
    __syncthreads();
    int pref = ((w > 0) ? wsum[w - 1] : 0) + inc - val;   // exclusive, chunk-local
    if (idx < n) off[idx] = pref;
    if (t == 1023) { bsum[chunk] = wsum[31]; __threadfence(); }
    __syncthreads();
    if (t == 0) islast = (atomicAdd(&g_scan_done, 1) == EB + VB - 1);
    __syncthreads();
    if (islast && w < 2) {
        __threadfence();   // acquire: see all blocks' bsum stores
        if (w == 0) {      // edges: EB <= 32, one warp-scan
            int v = (lane < EB) ? g_bsum_e[lane] : 0;
            int i2 = wscan(v);
            if (lane < EB) g_bsum_e[lane] = i2 - v;
        } else {           // vertices: VB <= 64, two tiles with carry
            int carry = 0;
#pragma unroll
            for (int tt = 0; tt < 2; tt++) {
                int id = tt * 32 + lane;
                int v = (id < VB) ? g_bsum_v[id] : 0;
                int i2 = wscan(v);
                if (id < VB) g_bsum_v[id] = carry + i2 - v;
                carry += __shfl_sync(0xffffffffu, i2, 31);
            }
        }
    }
}

// ------- fill member lists, 4 elems/thread, atomic-free -----------------------
__global__ void k_fill(int nnz) {
    int T = gridDim.x * blockDim.x;
    int i = blockIdx.x * blockDim.x + threadIdx.x;
    int j0 = i, j1 = i + T, j2 = i + 2 * T, j3 = i + 3 * T;
    bool b0 = j0 < nnz, b1 = j1 < nnz, b2 = j2 < nnz, b3 = j3 < nnz;
    int2 z = make_int2(0, 0);
    int2 pe0 = b0 ? g_pack_e[j0] : z, pv0 = b0 ? g_pack_v[j0] : z;
    int2 pe1 = b1 ? g_pack_e[j1] : z, pv1 = b1 ? g_pack_v[j1] : z;
    int2 pe2 = b2 ? g_pack_e[j2] : z, pv2 = b2 ? g_pack_v[j2] : z;
    int2 pe3 = b3 ? g_pack_e[j3] : z, pv3 = b3 ? g_pack_v[j3] : z;
    int oe0 = g_off_e[pe0.x] + g_bsum_e[pe0.x >> 10];
    int ov0 = g_off_v[pv0.x] + g_bsum_v[pv0.x >> 10];
    int oe1 = g_off_e[pe1.x] + g_bsum_e[pe1.x >> 10];
    int ov1 = g_off_v[pv1.x] + g_bsum_v[pv1.x >> 10];
    int oe2 = g_off_e[pe2.x] + g_bsum_e[pe2.x >> 10];
    int ov2 = g_off_v[pv2.x] + g_bsum_v[pv2.x >> 10];
    int oe3 = g_off_e[pe3.x] + g_bsum_e[pe3.x >> 10];
    int ov3 = g_off_v[pv3.x] + g_bsum_v[pv3.x >> 10];
    if (b0) { g_emem[oe0 + pe0.y] = pv0.x; g_vmem[ov0 + pv0.y] = pe0.x; }
    if (b1) { g_emem[oe1 + pe1.y] = pv1.x; g_vmem[ov1 + pv1.y] = pe1.x; }
    if (b2) { g_emem[oe2 + pe2.y] = pv2.x; g_vmem[ov2 + pv2.y] = pe2.x; }
    if (b3) { g_emem[oe3 + pe3.y] = pv3.x; g_vmem[ov3 + pv3.y] = pe3.x; }
}

// ---------------- per-edge mean of X (4 edges/block, 64 threads/edge, f4) -----
__global__ void k_sumx(const float* __restrict__ X) {
    int e = blockIdx.x * 4 + (threadIdx.x >> 6);
    int lane = threadIdx.x & 63;                   // channels [4*lane, 4*lane+4)
    int cnt = g_cnt_e[e];
    int base = g_off_e[e] + g_bsum_e[e >> 10];
    float4 a0 = make_float4(0.f, 0.f, 0.f, 0.f), a1 = a0, a2 = a0, a3 = a0;
    int j = 0;
    for (; j + 8 <= cnt; j += 8) {
        int v0 = g_emem[base + j + 0];
        int v1 = g_emem[base + j + 1];
        int v2 = g_emem[base + j + 2];
        int v3 = g_emem[base + j + 3];
        int v4 = g_emem[base + j + 4];
        int v5 = g_emem[base + j + 5];
        int v6 = g_emem[base + j + 6];
        int v7 = g_emem[base + j + 7];
        float4 x0 = ((const float4*)&X[v0 * IN_DIM])[lane];
        float4 x1 = ((const float4*)&X[v1 * IN_DIM])[lane];
        float4 x2 = ((const float4*)&X[v2 * IN_DIM])[lane];
        float4 x3 = ((const float4*)&X[v3 * IN_DIM])[lane];
        float4 x4 = ((const float4*)&X[v4 * IN_DIM])[lane];
        float4 x5 = ((const float4*)&X[v5 * IN_DIM])[lane];
        float4 x6 = ((const float4*)&X[v6 * IN_DIM])[lane];
        float4 x7 = ((const float4*)&X[v7 * IN_DIM])[lane];
        a0.x += x0.x + x4.x; a0.y += x0.y + x4.y; a0.z += x0.z + x4.z; a0.w += x0.w + x4.w;
        a1.x += x1.x + x5.x; a1.y += x1.y + x5.y; a1.z += x1.z + x5.z; a1.w += x1.w + x5.w;
        a2.x += x2.x + x6.x; a2.y += x2.y + x6.y; a2.z += x2.z + x6.z; a2.w += x2.w + x6.w;
        a3.x += x3.x + x7.x; a3.y += x3.y + x7.y; a3.z += x3.z + x7.z; a3.w += x3.w + x7.w;
    }
    for (; j + 4 <= cnt; j += 4) {
        int v0 = g_emem[base + j + 0];
        int v1 = g_emem[base + j + 1];
        int v2 = g_emem[base + j + 2];
        int v3 = g_emem[base + j + 3];
        float4 x0 = ((const float4*)&X[v0 * IN_DIM])[lane];
        float4 x1 = ((const float4*)&X[v1 * IN_DIM])[lane];
        float4 x2 = ((const float4*)&X[v2 * IN_DIM])[lane];
        float4 x3 = ((const float4*)&X[v3 * IN_DIM])[lane];
        a0.x += x0.x; a0.y += x0.y; a0.z += x0.z; a0.w += x0.w;
        a1.x += x1.x; a1.y += x1.y; a1.z += x1.z; a1.w += x1.w;
        a2.x += x2.x; a2.y += x2.y; a2.z += x2.z; a2.w += x2.w;
        a3.x += x3.x; a3.y += x3.y; a3.z += x3.z; a3.w += x3.w;
    }
    for (; j < cnt; j++) {
        float4 x0 = ((const float4*)&X[g_emem[base + j] * IN_DIM])[lane];
        a0.x += x0.x; a0.y += x0.y; a0.z += x0.z; a0.w += x0.w;
    }
    float inv = 1.0f / (float)(cnt > 0 ? cnt : 1);
    float4 r;
    r.x = (a0.x + a1.x + a2.x + a3.x) * inv;
    r.y = (a0.y + a1.y + a2.y + a3.y) * inv;
    r.z = (a0.z + a1.z + a2.z + a3.z) * inv;
    r.w = (a0.w + a1.w + a2.w + a3.w) * inv;
    ((float4*)&g_SumX[e * HC])[lane] = r;
}

// ------- Xe = SumX @ W^T + fused attention logits; Xe stored fp16 -------------
__global__ void k_gemm(const float* __restrict__ W, const float* __restrict__ att,
                       int E) {
    __shared__ __align__(16) float As[16][68];
    __shared__ __align__(16) float Bs[16][64];
    int tid = threadIdx.x;
    int tx = tid & 15, ty = tid >> 4;
    int lane = tid & 31;
    int row0 = blockIdx.y * 64, col0 = blockIdx.x * 64;
    unsigned long long c2[4][2] = {};
    int r = tid >> 2, sseg = tid & 3;
    float4 attv = *(const float4*)&att[col0 + tx * 4];

    for (int k0 = 0; k0 < IN_DIM; k0 += 16) {
        float4 av;
        int arow = row0 + r;
        if (arow < E) av = *(const float4*)&g_SumX[arow * HC + k0 + sseg * 4];
        else          av = make_float4(0.f, 0.f, 0.f, 0.f);
        As[sseg * 4 + 0][r] = av.x;
        As[sseg * 4 + 1][r] = av.y;
        As[sseg * 4 + 2][r] = av.z;
        As[sseg * 4 + 3][r] = av.w;
        float4 bv = *(const float4*)&W[(col0 + r) * IN_DIM + k0 + sseg * 4];
        Bs[sseg * 4 + 0][r] = bv.x;
        Bs[sseg * 4 + 1][r] = bv.y;
        Bs[sseg * 4 + 2][r] = bv.z;
        Bs[sseg * 4 + 3][r] = bv.w;
        __syncthreads();
#pragma unroll
        for (int kk = 0; kk < 16; kk++) {
            float4 a = *(const float4*)&As[kk][ty * 4];
            float4 b = *(const float4*)&Bs[kk][tx * 4];
            unsigned long long b01, b23, ap;
            PACK2(b01, b.x, b.y);
            PACK2(b23, b.z, b.w);
            PACK2(ap, a.x, a.x); FMA2(c2[0][0], ap, b01); FMA2(c2[0][1], ap, b23);
            PACK2(ap, a.y, a.y); FMA2(c2[1][0], ap, b01); FMA2(c2[1][1], ap, b23);
            PACK2(ap, a.z, a.z); FMA2(c2[2][0], ap, b01); FMA2(c2[2][1], ap, b23);
            PACK2(ap, a.w, a.w); FMA2(c2[3][0], ap, b01); FMA2(c2[3][1], ap, b23);
        }
        __syncthreads();
    }
#pragma unroll
    for (int i = 0; i < 4; i++) {
        int row = row0 + ty * 4 + i;
        float x0, x1, x2, x3;
        UNPACK2(x0, x1, c2[i][0]);
        UNPACK2(x2, x3, c2[i][1]);
        if (row < E) {
            __half2 h01 = __floats2half2_rn(x0, x1);
            __half2 h23 = __floats2half2_rn(x2, x3);
            uint2 st;
            st.x = *reinterpret_cast<unsigned*>(&h01);
            st.y = *reinterpret_cast<unsigned*>(&h23);
            *(uint2*)&g_Xe[row * HC + col0 + tx * 4] = st;
        }
        // fused alpha from fp32 accumulators
        float s = x0 * attv.x + x1 * attv.y + x2 * attv.z + x3 * attv.w;
        s += __shfl_xor_sync(0xffffffffu, s, 1);
        s += __shfl_xor_sync(0xffffffffu, s, 2);
        s += __shfl_xor_sync(0xffffffffu, s, 4);
        if ((lane & 7) == 0 && row < E) {
            int head = (col0 >> 5) + ((lane >> 3) & 1);
            g_alpha[row * H_ + head] = (s > 0.f) ? s : NEG_SLOPE * s;
        }
    }
}

// ---- per-vertex TWO-PASS softmax + weighted sum + L2 norm (R9 structure) -----
// 4 vertices / block, 64 threads / vertex; fp16 Xe loads in pass 2.
__global__ void k_final(float* __restrict__ out, int N) {
    int g = threadIdx.x >> 6;                  // vertex slot in block (0..3)
    int v = blockIdx.x * 4 + g;
    int lane = threadIdx.x & 63;               // channels [4*lane, 4*lane+4)
    int h = lane >> 3;
    __shared__ float red[8];
    float4 val = make_float4(0.f, 0.f, 0.f, 0.f);
    int deg = g_cnt_v[v];
    int base = g_off_v[v] + g_bsum_v[v >> 10];
    if (deg > 0) {
        float m = -3.4e38f;
        int j = 0;
        for (; j + 4 <= deg; j += 4) {
            int e0 = g_vmem[base + j + 0];
            int e1 = g_vmem[base + j + 1];
            int e2 = g_vmem[base + j + 2];
            int e3 = g_vmem[base + j + 3];
            float a0 = g_alpha[e0 * H_ + h];
            float a1 = g_alpha[e1 * H_ + h];
            float a2 = g_alpha[e2 * H_ + h];
            float a3 = g_alpha[e3 * H_ + h];
            m = fmaxf(m, fmaxf(fmaxf(a0, a1), fmaxf(a2, a3)));
        }
        for (; j < deg; j++)
            m = fmaxf(m, g_alpha[g_vmem[base + j] * H_ + h]);
        float s = 0.f;
        j = 0;
        for (; j + 4 <= deg; j += 4) {
            int e0 = g_vmem[base + j + 0];
            int e1 = g_vmem[base + j + 1];
            int e2 = g_vmem[base + j + 2];
            int e3 = g_vmem[base + j + 3];
            float w0 = __expf(g_alpha[e0 * H_ + h] - m);
            float w1 = __expf(g_alpha[e1 * H_ + h] - m);
            float w2 = __expf(g_alpha[e2 * H_ + h] - m);
            float w3 = __expf(g_alpha[e3 * H_ + h] - m);
            float4 x0 = xe_load(e0, lane);
            float4 x1 = xe_load(e1, lane);
            float4 x2 = xe_load(e2, lane);
            float4 x3 = xe_load(e3, lane);
            s += w0 + w1 + w2 + w3;
            val.x = fmaf(w0, x0.x, fmaf(w1, x1.x, fmaf(w2, x2.x, fmaf(w3, x3.x, val.x))));
            val.y = fmaf(w0, x0.y, fmaf(w1, x1.y, fmaf(w2, x2.y, fmaf(w3, x3.y, val.y))));
            val.z = fmaf(w0, x0.z, fmaf(w1, x1.z, fmaf(w2, x2.z, fmaf(w3, x3.z, val.z))));
            val.w = fmaf(w0, x0.w, fmaf(w1, x1.w, fmaf(w2, x2.w, fmaf(w3, x3.w, val.w))));
        }
        for (; j < deg; j++) {
            int e = g_vmem[base + j];
            float w = __expf(g_alpha[e * H_ + h] - m);
            s += w;
            float4 xe = xe_load(e, lane);
            val.x = fmaf(w, xe.x, val.x);
            val.y = fmaf(w, xe.y, val.y);
            val.z = fmaf(w, xe.z, val.z);
            val.w = fmaf(w, xe.w, val.w);
        }
        float inv = 1.0f / (s + 1e-16f);
        val.x *= inv; val.y *= inv; val.z *= inv; val.w *= inv;
    }
    float ss = val.x * val.x + val.y * val.y + val.z * val.z + val.w * val.w;
#pragma unroll
    for (int o = 16; o > 0; o >>= 1) ss += __shfl_down_sync(0xffffffffu, ss, o);
    if ((threadIdx.x & 31) == 0) red[threadIdx.x >> 5] = ss;
    __syncthreads();
    float tot = red[2 * g] + red[2 * g + 1];
    float scale = (tot > 0.f) ? rsqrtf(tot) : 0.f;
    val.x *= scale; val.y *= scale; val.z *= scale; val.w *= scale;
    ((float4*)&out[v * HC])[lane] = val;
}

// ---------------- host launch -------------------------------------------------
extern "C" void kernel_launch(void* const* d_in, const int* in_sizes, int n_in,
                              void* d_out, int out_size) {
    const float* X    = (const float*)d_in[0];
    const float* W    = (const float*)d_in[1];
    const float* att  = (const float*)d_in[2];
    const void*  vert = d_in[3];
    const void*  edge = d_in[4];

    int N   = in_sizes[0] / IN_DIM;
    int NNZ = in_sizes[3];
    int E   = EMAX;                 // fixed problem instance (num_edges = 10000)
    if (N   > NMAX)   N   = NMAX;
    if (NNZ > NNZMAX) NNZ = NNZMAX;

    k_zero<<<256, 256>>>((const int*)vert, NNZ, E, N);
    int g4 = ((NNZ + 3) / 4 + 255) / 256;      // 4 elems/thread
    k_hist<<<g4, 256>>>(vert, edge, NNZ);
    k_scan1<<<EB + VB, 1024>>>(E, N);
    k_fill<<<g4, 256>>>(NNZ);
    k_sumx<<<E / 4, 256>>>(X);
    dim3 gg(HC / 64, (E + 63) / 64);
    k_gemm<<<gg, 256>>>(W, att, E);
    k_final<<<N / 4, 256>>>((float*)d_out, N);
}